// round 3
// baseline (speedup 1.0000x reference)
#include <cuda_runtime.h>
#include <cstdint>

// Problem constants
#define BN   4096
#define TT   100
#define DD   784
#define HH   10
#define MM   (BN * TT)        // 409600 rows
#define NBH  (BN * HH)        // 40960

// proj kernel config
#define BLK  256              // threads per block
#define RPB  512              // rows per block (2 rows/thread)
#define KC   32               // K-chunk (floats)
#define NCH  25               // chunks (25*32 = 800 >= 784, zero-padded)
#define DEPTH 3               // cp.async pipeline depth
#define WS_STRIDE 800         // padded W row stride (floats)
#define XS_ELEMS (RPB * KC)   // floats per x buffer (16384)

#define ALPHA_F 0.8187307530779818f   // exp(-0.001/0.005)
#define BETA_F  0.9048374180359595f   // exp(-0.001/0.010)

// Scratch: proj[t][b][h], t-major so scan reads fully coalesced.
__device__ float g_proj[(size_t)TT * BN * HH];

// ---- packed f32x2 FMA (Blackwell FFMA2) ----
__device__ __forceinline__ void fma2(unsigned long long& acc,
                                     unsigned long long a,
                                     unsigned long long b) {
    asm("fma.rn.f32x2 %0, %1, %2, %0;" : "+l"(acc) : "l"(a), "l"(b));
}
__device__ __forceinline__ void unpk(float& lo, float& hi, unsigned long long v) {
    asm("mov.b64 {%0,%1}, %2;" : "=f"(lo), "=f"(hi) : "l"(v));
}

// ---- cp.async helpers ----
__device__ __forceinline__ void cp16(uint32_t saddr, const void* gptr, int src_size) {
    asm volatile("cp.async.cg.shared.global [%0], [%1], 16, %2;"
                 :: "r"(saddr), "l"(gptr), "r"(src_size));
}
__device__ __forceinline__ void cp_commit() { asm volatile("cp.async.commit_group;"); }
template <int N>
__device__ __forceinline__ void cp_wait() {
    asm volatile("cp.async.wait_group %0;" :: "n"(N) : "memory");
}

// ============================================================================
// Kernel 1: proj[t,b,h] = dot(x[b,t,:], W[h,:]) + bias[h]
// 2 rows/thread, W resident in smem, x triple-buffered via cp.async so two
// chunks are always in flight (hides DRAM latency+transfer behind compute).
// XOR-swizzled stride-32 x rows -> conflict-free LDS.128.
// ============================================================================
__global__ void __launch_bounds__(BLK, 1) proj_kernel(
    const float* __restrict__ x,
    const float* __restrict__ W,
    const float* __restrict__ bias)
{
    extern __shared__ float smem[];
    float* xs = smem;                       // [DEPTH][XS_ELEMS]
    float* ws = smem + DEPTH * XS_ELEMS;    // [HH][WS_STRIDE]

    const int tid = threadIdx.x;
    const int m0  = blockIdx.x * RPB;

    // ---- Stage W once: zero-fill (K padding), then copy 10x784 ----
    for (int i = tid; i < HH * WS_STRIDE / 4; i += BLK)
        ((float4*)ws)[i] = make_float4(0.f, 0.f, 0.f, 0.f);
    __syncthreads();
    for (int idx = tid; idx < HH * (DD / 4); idx += BLK) {
        int h = idx / (DD / 4);
        int q = idx - h * (DD / 4);
        ((float4*)(ws + h * WS_STRIDE))[q] = ((const float4*)(W + h * DD))[q];
    }

    // ---- x staging: chunk c -> buffer c % DEPTH, swizzled ----
    auto stage = [&](int c) {
        const int kb = c * KC;
        float* dst = xs + (c % DEPTH) * XS_ELEMS;
#pragma unroll
        for (int j = 0; j < 16; j++) {
            int idx = j * BLK + tid;       // 0..4095
            int row = idx >> 3;            // 0..511
            int c4  = idx & 7;             // 0..7
            int k   = kb + c4 * 4;
            int ok  = (k < DD) ? 16 : 0;
            const float* g = x + (size_t)(m0 + row) * DD + (ok ? k : 0);
            uint32_t s = (uint32_t)__cvta_generic_to_shared(
                dst + row * KC + ((c4 ^ (row & 7)) << 2));
            cp16(s, g, ok);
        }
    };

    // Prologue: chunks 0 and 1 in flight
    stage(0); cp_commit();
    stage(1); cp_commit();

    unsigned long long a0[HH], a1[HH];
#pragma unroll
    for (int h = 0; h < HH; h++) { a0[h] = 0ull; a1[h] = 0ull; }

    const int r0 = tid;
    const int r1 = tid + BLK;
    const int sw = r0 & 7;      // same for r1 (256 % 8 == 0)

    for (int c = 0; c < NCH; c++) {
        if (c > 0) __syncthreads();   // all threads done reading buf (c-1)%D
        if (c + 2 < NCH) {
            stage(c + 2);             // overwrites buf (c+2)%D == (c-1)%D
            cp_commit();
            cp_wait<2>();             // chunk c landed; c+1, c+2 pending
        } else if (c + 1 < NCH) {
            cp_wait<1>();             // chunk c landed; c+1 pending
        } else {
            cp_wait<0>();
        }
        __syncthreads();              // chunk c visible to all threads

        const float* xb = xs + (c % DEPTH) * XS_ELEMS;
        const int kb = c * KC;
#pragma unroll
        for (int i = 0; i < 8; i++) {
            ulonglong2 x0 = *(const ulonglong2*)&xb[r0 * KC + ((i ^ sw) << 2)];
            ulonglong2 x1 = *(const ulonglong2*)&xb[r1 * KC + ((i ^ sw) << 2)];
#pragma unroll
            for (int h = 0; h < HH; h++) {
                ulonglong2 wv = *(const ulonglong2*)&ws[h * WS_STRIDE + kb + i * 4];
                fma2(a0[h], x0.x, wv.x);
                fma2(a1[h], x1.x, wv.x);
                fma2(a0[h], x0.y, wv.y);
                fma2(a1[h], x1.y, wv.y);
            }
        }
    }

    // ---- Epilogue: reduce pairs, add bias, scatter to t-major proj ----
#pragma unroll
    for (int rr = 0; rr < 2; rr++) {
        int m  = m0 + tid + rr * BLK;
        int bb = m / TT;
        int tt = m - bb * TT;
        float* outp = g_proj + (size_t)tt * NBH + bb * HH;
        unsigned long long* acc = rr ? a1 : a0;
#pragma unroll
        for (int h = 0; h < HH; h++) {
            float lo, hi;
            unpk(lo, hi, acc[h]);
            outp[h] = lo + hi + __ldg(bias + h);
        }
    }
}

// ============================================================================
// Kernel 2: LIF scan, 2 lanes per thread (float2), prefetch 4 steps ahead.
// ============================================================================
__global__ void __launch_bounds__(128) scan_kernel(float* __restrict__ out)
{
    const int v = blockIdx.x * blockDim.x + threadIdx.x;   // 0..NBH/2-1
    const size_t MOFF2 = (size_t)(TT + 1) * NBH / 2;       // float2 units
    float2* o2 = (float2*)out;
    const float2* p2 = (const float2*)g_proj;

    float2 syn = make_float2(0.f, 0.f), mem = make_float2(0.f, 0.f);
    o2[v] = make_float2(0.f, 0.f);
    o2[MOFF2 + v] = make_float2(0.f, 0.f);

    float2 buf[4], nbuf[4];
#pragma unroll
    for (int j = 0; j < 4; j++) buf[j] = p2[(size_t)j * (NBH / 2) + v];

    for (int g = 0; g < TT / 4; g++) {
        if (g + 1 < TT / 4) {
#pragma unroll
            for (int j = 0; j < 4; j++)
                nbuf[j] = p2[(size_t)((g + 1) * 4 + j) * (NBH / 2) + v];
        }
#pragma unroll
        for (int j = 0; j < 4; j++) {
            int t = g * 4 + j;
            float sx = (mem.x > 1.0f) ? 1.0f : 0.0f;
            float sy = (mem.y > 1.0f) ? 1.0f : 0.0f;
            float nmx = BETA_F * mem.x + syn.x - sx;   // uses OLD syn
            float nmy = BETA_F * mem.y + syn.y - sy;
            syn.x = ALPHA_F * syn.x + buf[j].x;
            syn.y = ALPHA_F * syn.y + buf[j].y;
            o2[(size_t)(t + 1) * (NBH / 2) + v]         = make_float2(sx, sy);
            o2[MOFF2 + (size_t)(t + 1) * (NBH / 2) + v] = make_float2(nmx, nmy);
            mem.x = nmx;
            mem.y = nmy;
        }
#pragma unroll
        for (int j = 0; j < 4; j++) buf[j] = nbuf[j];
    }
}

// ============================================================================
extern "C" void kernel_launch(void* const* d_in, const int* in_sizes, int n_in,
                              void* d_out, int out_size)
{
    const float* x    = (const float*)d_in[0];
    const float* W    = (const float*)d_in[1];
    const float* bias = (const float*)d_in[2];
    float* out = (float*)d_out;

    const int smem_bytes = (DEPTH * XS_ELEMS + HH * WS_STRIDE) * sizeof(float); // 228608
    cudaFuncSetAttribute(proj_kernel,
                         cudaFuncAttributeMaxDynamicSharedMemorySize, smem_bytes);

    proj_kernel<<<MM / RPB, BLK, smem_bytes>>>(x, W, bias);
    scan_kernel<<<NBH / 2 / 128, 128>>>(out);
}

// round 4
// speedup vs baseline: 1.6407x; 1.6407x over previous
#include <cuda_runtime.h>
#include <cstdint>

// Problem constants
#define BN   4096
#define TT   100
#define DD   784
#define HH   10
#define MM   (BN * TT)        // 409600 rows
#define NBH  (BN * HH)        // 40960

// proj kernel config — sized so 2 CTAs fit per SM (latency hiding via CTA ILP)
#define BLK  128              // threads per block
#define RPB  256              // rows per block (2 rows/thread)
#define KC   32               // K-chunk (floats)
#define NCH  25               // chunks (25*32 = 800 >= 784, zero-padded)
#define WS_STRIDE 800         // padded W row stride (floats)
#define XS_ELEMS (RPB * KC)   // floats per x buffer (8192)

#define ALPHA_F 0.8187307530779818f   // exp(-0.001/0.005)
#define BETA_F  0.9048374180359595f   // exp(-0.001/0.010)

// Scratch: proj[t][b][h], t-major so scan reads fully coalesced.
__device__ float g_proj[(size_t)TT * BN * HH];

// ---- packed f32x2 FMA (Blackwell FFMA2) ----
__device__ __forceinline__ void fma2(unsigned long long& acc,
                                     unsigned long long a,
                                     unsigned long long b) {
    asm("fma.rn.f32x2 %0, %1, %2, %0;" : "+l"(acc) : "l"(a), "l"(b));
}
__device__ __forceinline__ void unpk(float& lo, float& hi, unsigned long long v) {
    asm("mov.b64 {%0,%1}, %2;" : "=f"(lo), "=f"(hi) : "l"(v));
}

// ---- cp.async helpers ----
__device__ __forceinline__ void cp16(uint32_t saddr, const void* gptr, int src_size) {
    asm volatile("cp.async.cg.shared.global [%0], [%1], 16, %2;"
                 :: "r"(saddr), "l"(gptr), "r"(src_size));
}
__device__ __forceinline__ void cp_commit() { asm volatile("cp.async.commit_group;"); }
__device__ __forceinline__ void cp_wait1()  { asm volatile("cp.async.wait_group 1;" ::: "memory"); }
__device__ __forceinline__ void cp_wait0()  { asm volatile("cp.async.wait_group 0;" ::: "memory"); }

// ============================================================================
// Kernel 1: proj[t,b,h] = dot(x[b,t,:], W[h,:]) + bias[h]
// 2 rows/thread, W resident in smem, x double-buffered via cp.async.
// 95.25 KB smem/CTA -> 2 CTAs/SM: one CTA computes while the other's chunk
// is in flight, hiding DRAM latency without deep per-CTA queues.
// ============================================================================
__global__ void __launch_bounds__(BLK, 2) proj_kernel(
    const float* __restrict__ x,
    const float* __restrict__ W,
    const float* __restrict__ bias)
{
    extern __shared__ float smem[];
    float* xs = smem;                   // [2][XS_ELEMS]
    float* ws = smem + 2 * XS_ELEMS;    // [HH][WS_STRIDE]

    const int tid = threadIdx.x;
    const int m0  = blockIdx.x * RPB;

    // ---- Stage W once: zero-fill (K padding), then copy 10x784 ----
    for (int i = tid; i < HH * WS_STRIDE / 4; i += BLK)
        ((float4*)ws)[i] = make_float4(0.f, 0.f, 0.f, 0.f);
    __syncthreads();
    for (int idx = tid; idx < HH * (DD / 4); idx += BLK) {
        int h = idx / (DD / 4);
        int q = idx - h * (DD / 4);
        ((float4*)(ws + h * WS_STRIDE))[q] = ((const float4*)(W + h * DD))[q];
    }

    // ---- x staging: chunk c -> buffer (c&1), XOR-swizzled rows ----
    auto stage = [&](int c) {
        const int kb   = c * KC;
        float* dst = xs + (c & 1) * XS_ELEMS;
#pragma unroll
        for (int j = 0; j < 16; j++) {
            int idx = j * BLK + tid;       // 0..2047
            int row = idx >> 3;            // 0..255
            int c4  = idx & 7;             // 0..7
            int k   = kb + c4 * 4;
            int ok  = (k < DD) ? 16 : 0;
            const float* g = x + (size_t)(m0 + row) * DD + (ok ? k : 0);
            uint32_t s = (uint32_t)__cvta_generic_to_shared(
                dst + row * KC + ((c4 ^ (row & 7)) << 2));
            cp16(s, g, ok);
        }
    };

    // Prologue: chunk 0 in flight
    stage(0);
    cp_commit();

    unsigned long long a0[HH], a1[HH];
#pragma unroll
    for (int h = 0; h < HH; h++) { a0[h] = 0ull; a1[h] = 0ull; }

    const int r0 = tid;
    const int r1 = tid + BLK;
    const int sw = r0 & 7;      // same for r1 (128 % 8 == 0)

    for (int c = 0; c < NCH; c++) {
        __syncthreads();                 // everyone done reading buffer (c+1)&1
        if (c + 1 < NCH) {
            stage(c + 1);
            cp_commit();
            cp_wait1();                  // chunk c complete, c+1 in flight
        } else {
            cp_wait0();
        }
        __syncthreads();                 // chunk c visible to all threads

        const float* xb = xs + (c & 1) * XS_ELEMS;
        const int kb = c * KC;
#pragma unroll
        for (int i = 0; i < 8; i++) {
            ulonglong2 x0 = *(const ulonglong2*)&xb[r0 * KC + ((i ^ sw) << 2)];
            ulonglong2 x1 = *(const ulonglong2*)&xb[r1 * KC + ((i ^ sw) << 2)];
#pragma unroll
            for (int h = 0; h < HH; h++) {
                ulonglong2 wv = *(const ulonglong2*)&ws[h * WS_STRIDE + kb + i * 4];
                fma2(a0[h], x0.x, wv.x);
                fma2(a1[h], x1.x, wv.x);
                fma2(a0[h], x0.y, wv.y);
                fma2(a1[h], x1.y, wv.y);
            }
        }
    }

    // ---- Epilogue: reduce pairs, add bias, scatter to t-major proj ----
#pragma unroll
    for (int rr = 0; rr < 2; rr++) {
        int m  = m0 + tid + rr * BLK;
        int bb = m / TT;
        int tt = m - bb * TT;
        float* outp = g_proj + (size_t)tt * NBH + bb * HH;
        unsigned long long* acc = rr ? a1 : a0;
#pragma unroll
        for (int h = 0; h < HH; h++) {
            float lo, hi;
            unpk(lo, hi, acc[h]);
            outp[h] = lo + hi + __ldg(bias + h);
        }
    }
}

// ============================================================================
// Kernel 2: LIF scan, one thread per (b,h) lane, prefetch 4 steps ahead.
// (round-2 proven version)
// ============================================================================
__global__ void __launch_bounds__(256) scan_kernel(float* __restrict__ out)
{
    const int u = blockIdx.x * blockDim.x + threadIdx.x;   // 0..NBH-1
    const size_t MOFF = (size_t)(TT + 1) * NBH;

    float syn = 0.f, mem = 0.f;
    out[u] = 0.f;
    out[MOFF + u] = 0.f;

    float buf[4], nbuf[4];
#pragma unroll
    for (int j = 0; j < 4; j++) buf[j] = g_proj[(size_t)j * NBH + u];

    for (int g = 0; g < TT / 4; g++) {
        if (g + 1 < TT / 4) {
#pragma unroll
            for (int j = 0; j < 4; j++)
                nbuf[j] = g_proj[(size_t)((g + 1) * 4 + j) * NBH + u];
        }
#pragma unroll
        for (int j = 0; j < 4; j++) {
            int t = g * 4 + j;
            float mthr  = mem - 1.0f;
            float spike = (mthr > 0.0f) ? 1.0f : 0.0f;
            float nsyn  = ALPHA_F * syn + buf[j];
            float nmem  = BETA_F * mem + syn - spike;   // uses OLD syn
            out[(size_t)(t + 1) * NBH + u]        = spike;
            out[MOFF + (size_t)(t + 1) * NBH + u] = nmem;
            syn = nsyn;
            mem = nmem;
        }
#pragma unroll
        for (int j = 0; j < 4; j++) buf[j] = nbuf[j];
    }
}

// ============================================================================
extern "C" void kernel_launch(void* const* d_in, const int* in_sizes, int n_in,
                              void* d_out, int out_size)
{
    const float* x    = (const float*)d_in[0];
    const float* W    = (const float*)d_in[1];
    const float* bias = (const float*)d_in[2];
    float* out = (float*)d_out;

    const int smem_bytes = (2 * XS_ELEMS + HH * WS_STRIDE) * sizeof(float); // 97536
    cudaFuncSetAttribute(proj_kernel,
                         cudaFuncAttributeMaxDynamicSharedMemorySize, smem_bytes);

    proj_kernel<<<MM / RPB, BLK, smem_bytes>>>(x, W, bias);
    scan_kernel<<<NBH / 256, 256>>>(out);
}

// round 5
// speedup vs baseline: 1.8092x; 1.1028x over previous
#include <cuda_runtime.h>
#include <cstdint>

// Problem constants
#define BN   4096
#define TT   100
#define DD   784           // = 49 * 16, exact
#define HH   10
#define MM   (BN * TT)     // 409600 rows
#define NBH  (BN * HH)     // 40960

// proj kernel config
#define BLK  128           // threads per block (4 warps)
#define RPB  256           // rows per block (2 rows/thread)
#define KC   16            // K-chunk (floats)  -> 49 exact chunks
#define NCH  (DD / KC)     // 49
#define RS   20            // smem row stride in floats (16 + 4 pad; 5 coprime 8)
#define XSE  (RPB * RS)    // floats per x buffer (5120)

#define ALPHA_F 0.8187307530779818f   // exp(-0.001/0.005)
#define BETA_F  0.9048374180359595f   // exp(-0.001/0.010)

// Scratch: proj[t][b][h], t-major so scan reads fully coalesced.
__device__ float g_proj[(size_t)TT * BN * HH];

// ---- packed f32x2 FMA (Blackwell FFMA2) ----
__device__ __forceinline__ void fma2(unsigned long long& acc,
                                     unsigned long long a,
                                     unsigned long long b) {
    asm("fma.rn.f32x2 %0, %1, %2, %0;" : "+l"(acc) : "l"(a), "l"(b));
}
__device__ __forceinline__ void unpk(float& lo, float& hi, unsigned long long v) {
    asm("mov.b64 {%0,%1}, %2;" : "=f"(lo), "=f"(hi) : "l"(v));
}

// ---- cp.async helpers ----
__device__ __forceinline__ void cp16(uint32_t saddr, const void* gptr) {
    asm volatile("cp.async.cg.shared.global [%0], [%1], 16;"
                 :: "r"(saddr), "l"(gptr));
}
__device__ __forceinline__ void cp_commit() { asm volatile("cp.async.commit_group;"); }
template <int N>
__device__ __forceinline__ void cp_wait() {
    asm volatile("cp.async.wait_group %0;" :: "n"(N) : "memory");
}

// ============================================================================
// Kernel 1: proj[t,b,h] = dot(x[b,t,:], W[h,:]) + bias[h]
// Warp-autonomous pipelines: each warp cp.asyncs its OWN 64 rows into a
// warp-private smem region, so the chunk loop needs only wait_group +
// __syncwarp — NO block barriers. W resident in smem (broadcast LDS).
// 72.3 KB smem/CTA -> 3 CTAs/SM, 3 warps/SMSP interleaving.
// ============================================================================
__global__ void __launch_bounds__(BLK, 3) proj_kernel(
    const float* __restrict__ x,
    const float* __restrict__ W,
    const float* __restrict__ bias)
{
    extern __shared__ float smem[];
    float* xs = smem;                 // [2][XSE]
    float* ws = smem + 2 * XSE;       // [HH][DD], natural stride 784

    const int tid  = threadIdx.x;
    const int lane = tid & 31;
    const int wb   = tid & ~31;       // warp base (0,32,64,96)
    const int m0   = blockIdx.x * RPB;

    // ---- Stage W once (read-only thereafter; one block barrier total) ----
    for (int i = tid; i < HH * DD / 4; i += BLK)
        ((float4*)ws)[i] = ((const float4*)W)[i];
    __syncthreads();

    // ---- per-warp x staging: chunk c -> buffer (c&1), warp-private rows ----
    auto stage = [&](int c) {
        const int kb = c * KC;
        float* dst = xs + (c & 1) * XSE;
#pragma unroll
        for (int j = 0; j < 8; j++) {
            int u   = j * 32 + lane;              // 0..255
            int rl  = u >> 2;                     // 0..63 (warp-local row)
            int c4  = u & 3;                      // 16B unit within chunk
            int slot = (rl < 32) ? (wb + rl) : (BLK + wb + rl - 32);
            const float* g = x + (size_t)(m0 + slot) * DD + kb + c4 * 4;
            uint32_t s = (uint32_t)__cvta_generic_to_shared(
                dst + slot * RS + c4 * 4);
            cp16(s, g);
        }
    };

    stage(0); cp_commit();

    unsigned long long a0[HH], a1[HH];
#pragma unroll
    for (int h = 0; h < HH; h++) { a0[h] = 0ull; a1[h] = 0ull; }

    for (int c = 0; c < NCH; c++) {
        if (c + 1 < NCH) {
            stage(c + 1);
            cp_commit();
            cp_wait<1>();             // chunk c landed (this warp's copies)
        } else {
            cp_wait<0>();
        }
        __syncwarp();                 // cross-lane visibility within warp

        const float* xb = xs + (c & 1) * XSE;
        // Load this thread's two 16-float row chunks (4 x 16B each)
        ulonglong2 x0[4], x1[4];
#pragma unroll
        for (int i = 0; i < 4; i++) {
            x0[i] = *(const ulonglong2*)&xb[tid * RS + i * 4];
            x1[i] = *(const ulonglong2*)&xb[(tid + BLK) * RS + i * 4];
        }
        const int kb = c * KC;
#pragma unroll
        for (int h = 0; h < HH; h++) {
            const float* wp = ws + h * DD + kb;
#pragma unroll
            for (int i = 0; i < 4; i++) {
                ulonglong2 wv = *(const ulonglong2*)(wp + i * 4);
                fma2(a0[h], x0[i].x, wv.x);
                fma2(a1[h], x1[i].x, wv.x);
                fma2(a0[h], x0[i].y, wv.y);
                fma2(a1[h], x1[i].y, wv.y);
            }
        }
        __syncwarp();                 // all lanes done reading buf (c&1)
    }

    // ---- Epilogue: reduce pairs, add bias, scatter to t-major proj ----
#pragma unroll
    for (int rr = 0; rr < 2; rr++) {
        int m  = m0 + tid + rr * BLK;
        int bb = m / TT;
        int tt = m - bb * TT;
        float* outp = g_proj + (size_t)tt * NBH + bb * HH;
        unsigned long long* acc = rr ? a1 : a0;
#pragma unroll
        for (int h = 0; h < HH; h++) {
            float lo, hi;
            unpk(lo, hi, acc[h]);
            outp[h] = lo + hi + __ldg(bias + h);
        }
    }
}

// ============================================================================
// Kernel 2: LIF scan, one thread per (b,h) lane, prefetch 4 steps ahead.
// 128 blocks x 320 threads = 40960 lanes exactly; <=1 block/SM -> balanced.
// ============================================================================
__global__ void __launch_bounds__(320) scan_kernel(float* __restrict__ out)
{
    const int u = blockIdx.x * 320 + threadIdx.x;   // 0..NBH-1
    const size_t MOFF = (size_t)(TT + 1) * NBH;

    float syn = 0.f, mem = 0.f;
    out[u] = 0.f;
    out[MOFF + u] = 0.f;

    float buf[4], nbuf[4];
#pragma unroll
    for (int j = 0; j < 4; j++) buf[j] = g_proj[(size_t)j * NBH + u];

    for (int g = 0; g < TT / 4; g++) {
        if (g + 1 < TT / 4) {
#pragma unroll
            for (int j = 0; j < 4; j++)
                nbuf[j] = g_proj[(size_t)((g + 1) * 4 + j) * NBH + u];
        }
#pragma unroll
        for (int j = 0; j < 4; j++) {
            int t = g * 4 + j;
            float mthr  = mem - 1.0f;
            float spike = (mthr > 0.0f) ? 1.0f : 0.0f;
            float nsyn  = ALPHA_F * syn + buf[j];
            float nmem  = BETA_F * mem + syn - spike;   // uses OLD syn
            out[(size_t)(t + 1) * NBH + u]        = spike;
            out[MOFF + (size_t)(t + 1) * NBH + u] = nmem;
            syn = nsyn;
            mem = nmem;
        }
#pragma unroll
        for (int j = 0; j < 4; j++) buf[j] = nbuf[j];
    }
}

// ============================================================================
extern "C" void kernel_launch(void* const* d_in, const int* in_sizes, int n_in,
                              void* d_out, int out_size)
{
    const float* x    = (const float*)d_in[0];
    const float* W    = (const float*)d_in[1];
    const float* bias = (const float*)d_in[2];
    float* out = (float*)d_out;

    const int smem_bytes = (2 * XSE + HH * DD) * sizeof(float); // 72320
    cudaFuncSetAttribute(proj_kernel,
                         cudaFuncAttributeMaxDynamicSharedMemorySize, smem_bytes);

    proj_kernel<<<MM / RPB, BLK, smem_bytes>>>(x, W, bias);
    scan_kernel<<<NBH / 320, 320>>>(out);
}